// round 16
// baseline (speedup 1.0000x reference)
#include <cuda_runtime.h>
#include <math.h>

#define NB 16
#define NC 80
#define NLOC 17064
#define NBUCK 4096
#define SEL_CAP 4096
#define TOPK 1000
#define MAXDET 100

// ---------------- static device scratch (no allocations) ----------------
__device__ int g_hist[NB * NBUCK];
__device__ int g_selCount[NB];
__device__ int g_done[NB];
__device__ int g_thr[NB];
__device__ float g_thrX[NB];
__device__ float g_cen[NB * NLOC];
__device__ unsigned long long g_sel[NB * SEL_CAP];   // (score_bits<<32)|(~idx)

// ---------------- init: zero hist/counters + centerness sigmoid ----------------
__global__ __launch_bounds__(256) void init_kernel(
    const float* __restrict__ ct0, const float* __restrict__ ct1,
    const float* __restrict__ ct2, const float* __restrict__ ct3,
    const float* __restrict__ ct4)
{
    int b = blockIdx.y;
    int bx = blockIdx.x;
    int t = threadIdx.x;
    if (bx < 16) g_hist[b * NBUCK + bx * 256 + t] = 0;
    if (bx == 0 && t == 0) { g_selCount[b] = 0; g_done[b] = 0; }
    int loc = bx * 256 + t;
    if (loc >= NLOC) return;
    const float* p; int local;
    if      (loc < 12800) { p = ct0 + b * 12800; local = loc; }
    else if (loc < 16000) { p = ct1 + b * 3200;  local = loc - 12800; }
    else if (loc < 16800) { p = ct2 + b * 800;   local = loc - 16000; }
    else if (loc < 17008) { p = ct3 + b * 208;   local = loc - 16800; }
    else                  { p = ct4 + b * 56;    local = loc - 17008; }
    float x = p[local];
    g_cen[b * NLOC + loc] = __fdividef(1.0f, 1.0f + __expf(-x));
}

// ---------------- pass A: histogram (smem-staged) + fused threshold ----------------
template<int HW, int LOCOFF>
__device__ __forceinline__ void hist_level(
    const float* __restrict__ lg, int b, int chunk, int* sh)
{
    constexpr int CHW = NC * HW;
    const float* lp = lg + (size_t)b * CHW;
    const float* cenp = g_cen + b * NLOC + LOCOFF;
    int e0 = chunk * 4096 + threadIdx.x * 4;
    float4 v[4];
    #pragma unroll
    for (int k = 0; k < 4; k++) {
        int e = e0 + k * 1024;
        v[k] = make_float4(-9e9f, -9e9f, -9e9f, -9e9f);
        if (e < CHW) v[k] = *reinterpret_cast<const float4*>(lp + e);
    }
    #pragma unroll
    for (int k = 0; k < 4; k++) {
        int e = e0 + k * 1024;
        int c  = e / HW;
        int hw = e - c * HW;
        float xs[4] = {v[k].x, v[k].y, v[k].z, v[k].w};
        #pragma unroll
        for (int i = 0; i < 4; i++) {
            float x = xs[i];
            if (x > -2.9445f) {                  // sigmoid(-2.9445) < 0.05 w/ margin
                float cls = __fdividef(1.0f, 1.0f + __expf(-x));
                if (cls > 0.05f) {
                    float comb = cls * cenp[hw + i];
                    atomicAdd(&sh[__float_as_uint(comb) >> 19], 1);
                }
            }
        }
    }
}

__global__ __launch_bounds__(256) void histA_kernel(
    const float* __restrict__ lg0, const float* __restrict__ lg1,
    const float* __restrict__ lg2, const float* __restrict__ lg3,
    const float* __restrict__ lg4)
{
    __shared__ int sh[NBUCK];
    __shared__ int s_last;
    int t = threadIdx.x;
    #pragma unroll
    for (int q = 0; q < NBUCK / 256; q++) sh[q * 256 + t] = 0;
    __syncthreads();

    int bx = blockIdx.x, b = blockIdx.y;
    if      (bx < 250) hist_level<12800,     0>(lg0, b, bx,       sh);
    else if (bx < 313) hist_level< 3200, 12800>(lg1, b, bx - 250, sh);
    else if (bx < 329) hist_level<  800, 16000>(lg2, b, bx - 313, sh);
    else if (bx < 334) hist_level<  208, 16800>(lg3, b, bx - 329, sh);
    else               hist_level<   56, 17008>(lg4, b, bx - 334, sh);
    __syncthreads();

    int* gh = &g_hist[b * NBUCK];
    #pragma unroll
    for (int q = 0; q < NBUCK / 256; q++) {
        int v = sh[q * 256 + t];
        if (v) atomicAdd(&gh[q * 256 + t], v);
    }

    // fused threshold: last block of this batch scans the histogram
    __threadfence();
    if (t == 0) s_last = (atomicAdd(&g_done[b], 1) == 335);
    __syncthreads();
    if (!s_last) return;

    int s = 0;
    for (int r = t * 16; r < t * 16 + 16; r++)
        s += gh[NBUCK - 1 - r];
    sh[t] = s;
    __syncthreads();
    if (t == 0) {
        int cum = 0, j = 255;
        for (int q = 0; q < 256; q++) {
            if (cum + sh[q] >= TOPK) { j = q; break; }
            cum += sh[q];
        }
        sh[300] = j; sh[301] = cum;
    }
    __syncthreads();
    int j = sh[300];
    if (t < 16) sh[256 + t] = gh[NBUCK - 1 - (j * 16 + t)];
    __syncthreads();
    if (t == 0) {
        int cum = sh[301], thr = 0;
        for (int q = 0; q < 16; q++) {
            cum += sh[256 + q];
            if (cum >= TOPK) { thr = NBUCK - 1 - (j * 16 + q); break; }
        }
        g_thr[b] = thr;                          // 0 => take everything
        float tX = -2.9445f;
        if (thr > 0) {
            float cm = __uint_as_float((unsigned)thr << 19);  // bucket lower edge
            if (cm > 0.0f && cm < 1.0f)
                tX = fmaxf(tX, logf(cm / (1.0f - cm)) - 1e-3f); // cls >= comb >= cm
        }
        g_thrX[b] = tX;
    }
}

// ---------------- pass B: selective re-read, direct candidate write ----------------
template<int HW, int LOCOFF>
__device__ __forceinline__ void sel_level(
    const float* __restrict__ lg, int b, int chunk, unsigned thr, float thrX)
{
    constexpr int CHW = NC * HW;
    const float* lp = lg + (size_t)b * CHW;
    const float* cenp = g_cen + b * NLOC + LOCOFF;
    int e0 = chunk * 4096 + threadIdx.x * 4;
    float4 v[4];
    #pragma unroll
    for (int k = 0; k < 4; k++) {
        int e = e0 + k * 1024;
        v[k] = make_float4(-9e9f, -9e9f, -9e9f, -9e9f);
        if (e < CHW) v[k] = *reinterpret_cast<const float4*>(lp + e);
    }
    #pragma unroll
    for (int k = 0; k < 4; k++) {
        int e = e0 + k * 1024;
        int c  = e / HW;
        int hw = e - c * HW;
        float xs[4] = {v[k].x, v[k].y, v[k].z, v[k].w};
        #pragma unroll
        for (int i = 0; i < 4; i++) {
            float x = xs[i];
            if (x > thrX) {
                float cls = __fdividef(1.0f, 1.0f + __expf(-x));
                if (cls > 0.05f) {
                    float comb = cls * cenp[hw + i];
                    unsigned bits = __float_as_uint(comb);
                    if ((bits >> 19) >= thr) {
                        unsigned idx = (unsigned)((LOCOFF + hw + i) * NC + c);
                        int p = atomicAdd(&g_selCount[b], 1);
                        if (p < SEL_CAP)
                            g_sel[b * SEL_CAP + p] =
                                ((unsigned long long)bits << 32) |
                                (unsigned long long)(0xFFFFFFFFu - idx);
                    }
                }
            }
        }
    }
}

__global__ __launch_bounds__(256) void selB_kernel(
    const float* __restrict__ lg0, const float* __restrict__ lg1,
    const float* __restrict__ lg2, const float* __restrict__ lg3,
    const float* __restrict__ lg4)
{
    int bx = blockIdx.x, b = blockIdx.y;
    unsigned thr = (unsigned)g_thr[b];
    float thrX = g_thrX[b];
    if      (bx < 250) sel_level<12800,     0>(lg0, b, bx,       thr, thrX);
    else if (bx < 313) sel_level< 3200, 12800>(lg1, b, bx - 250, thr, thrX);
    else if (bx < 329) sel_level<  800, 16000>(lg2, b, bx - 313, thr, thrX);
    else if (bx < 334) sel_level<  208, 16800>(lg3, b, bx - 329, thr, thrX);
    else               sel_level<   56, 17008>(lg4, b, bx - 334, thr, thrX);
}

// ---------------- fused radix-select + 1024-sort + decode + 256-thread NMS ----------------
#define BAR256() asm volatile("bar.sync 1, 256;" ::: "memory")

__global__ __launch_bounds__(1024) void sortnms_kernel(
    const float* __restrict__ bb0, const float* __restrict__ bb1,
    const float* __restrict__ bb2, const float* __restrict__ bb3,
    const float* __restrict__ bb4, const float* __restrict__ iminfo,
    float* __restrict__ out)
{
    int b = blockIdx.x;
    int t = threadIdx.x;
    int lane = t & 31;

    __shared__ union {
        unsigned long long key[SEL_CAP];                  // 32 KB
        struct { float4 pbox[1024];                       // 16 KB plain clipped coords
                 float ar[1024], sc[1024], cf[1024]; } d; // 12 KB
    } u;
    __shared__ unsigned long long buf[1024];              // 8 KB
    __shared__ unsigned s_alive[32];
    __shared__ int s_best;
    __shared__ float s_bestS;
    __shared__ unsigned long long s_pivot;
    __shared__ int s_kneed, s_c2;
    __shared__ int h256[256];

    // pre-zero this batch's output (100 rows x 6)
    if (t < MAXDET * 6) out[(size_t)b * MAXDET * 6 + t] = 0.0f;

    int cnt = min(g_selCount[b], SEL_CAP);
    buf[t] = 0ULL;
    for (int i = t; i < cnt; i += 1024)
        u.key[i] = g_sel[b * SEL_CAP + i];
    if (t == 0) { s_pivot = 0ULL; s_kneed = TOPK; s_c2 = 0; }
    __syncthreads();

    if (cnt > 1024) {
        // exact radix-select: 1000th-largest 64-bit key (keys unique)
        for (int byte = 7; byte >= 0; byte--) {
            if (t < 256) h256[t] = 0;
            __syncthreads();
            unsigned long long piv = s_pivot;
            int shb = byte * 8;
            unsigned long long himask = (byte == 7) ? 0ULL
                : (0xFFFFFFFFFFFFFFFFULL << (8 * (byte + 1)));
            for (int i = t; i < cnt; i += 1024) {
                unsigned long long kk = u.key[i];
                if ((kk & himask) == piv)
                    atomicAdd(&h256[(int)((kk >> shb) & 0xFF)], 1);
            }
            __syncthreads();
            if (t < 32) {
                int g0 = 255 - 8 * t;
                int gs = 0;
                #pragma unroll
                for (int q = 0; q < 8; q++) gs += h256[g0 - q];
                int pre = gs;
                #pragma unroll
                for (int d = 1; d < 32; d <<= 1) {
                    int x = __shfl_up_sync(0xFFFFFFFFu, pre, d);
                    if (t >= d) pre += x;
                }
                int excl = pre - gs;
                int k = s_kneed;
                bool hit = (excl < k) && (excl + gs >= k);
                if (hit) {
                    int need = k - excl, acc = 0;
                    #pragma unroll
                    for (int q = 0; q < 8; q++) {
                        int c = h256[g0 - q];
                        if (acc + c >= need) {
                            s_pivot = piv | ((unsigned long long)(g0 - q) << shb);
                            s_kneed = need - acc;
                            break;
                        }
                        acc += c;
                    }
                }
            }
            __syncthreads();
        }
        // compact exactly TOPK keys >= pivot
        unsigned long long piv = s_pivot;
        for (int i = t; (i - lane) < cnt; i += 1024) {
            bool take = (i < cnt) && (u.key[i] >= piv);
            unsigned m = __ballot_sync(0xFFFFFFFFu, take);
            if (m) {
                int leader = __ffs(m) - 1;
                int base = 0;
                if (lane == leader) base = atomicAdd(&s_c2, __popc(m));
                base = __shfl_sync(0xFFFFFFFFu, base, leader);
                if (take) {
                    int p = base + __popc(m & ((1u << lane) - 1u));
                    if (p < 1024) buf[p] = u.key[i];
                }
            }
        }
    } else {
        if (t < cnt) buf[t] = u.key[t];
    }
    __syncthreads();

    // register-resident bitonic sort of 1024 (descending)
    unsigned long long v = buf[t];
    for (int k = 2; k <= 1024; k <<= 1) {
        bool desc = (t & k) == 0;
        for (int j = k >> 1; j > 0; j >>= 1) {
            unsigned long long p;
            if (j >= 32) {
                __syncthreads();
                buf[t] = v;
                __syncthreads();
                p = buf[t ^ j];
            } else {
                p = __shfl_xor_sync(0xFFFFFFFFu, v, j);
            }
            bool keepmax = ((t & j) == 0) == desc;
            bool pgt = p > v;
            if (pgt == keepmax) v = p;
        }
    }
    unsigned long long myKey = v;          // rank t (desc score, asc idx ties)
    __syncthreads();                       // sort reads done; arrays may overwrite key

    // decode into smem arrays (all 1024 ranks; ranks >= 1000 never used by NMS)
    {
        unsigned bits = (unsigned)(myKey >> 32);
        float x1 = 0.f, y1 = 0.f, x2 = 0.f, y2 = 0.f, sc = 0.f, cf = 0.f;
        if (bits != 0u) {
            unsigned idx = 0xFFFFFFFFu - (unsigned)(myKey & 0xFFFFFFFFu);
            int loc = (int)(idx / NC);
            int c   = (int)(idx % NC);
            const int offs[5]    = {0, 12800, 16000, 16800, 17008};
            const int Ws[5]      = {128, 64, 32, 16, 8};
            const int HWs[5]     = {12800, 3200, 800, 208, 56};
            const int strides[5] = {8, 16, 32, 64, 128};
            const float* bbs[5]  = {bb0, bb1, bb2, bb3, bb4};
            int lvl = 4;
            if      (loc < 12800) lvl = 0;
            else if (loc < 16000) lvl = 1;
            else if (loc < 16800) lvl = 2;
            else if (loc < 17008) lvl = 3;
            int local = loc - offs[lvl];
            int W = Ws[lvl], HW = HWs[lvl], st = strides[lvl];
            int hh = local / W;
            int ww = local - hh * W;
            float cx = (float)(ww * st + (st >> 1));
            float cy = (float)(hh * st + (st >> 1));
            const float* bp = bbs[lvl] + (size_t)b * 4 * HW + local;
            float r0 = bp[0], r1 = bp[HW], r2 = bp[2 * HW], r3 = bp[3 * HW];
            float ih = iminfo[b * 2 + 0];
            float iw = iminfo[b * 2 + 1];
            x1 = fminf(fmaxf(cx - r0, 0.0f), iw - 1.0f);
            y1 = fminf(fmaxf(cy - r1, 0.0f), ih - 1.0f);
            x2 = fminf(fmaxf(cx + r2, 0.0f), iw - 1.0f);
            y2 = fminf(fmaxf(cy + r3, 0.0f), ih - 1.0f);
            sc = sqrtf(__uint_as_float(bits) + 1e-12f);
            cf = (float)c;
        }
        float off = cf * 10000.0f;
        float ox1 = x1 + off, oy1 = y1 + off, ox2 = x2 + off, oy2 = y2 + off;
        u.d.pbox[t] = make_float4(x1, y1, x2, y2);
        u.d.ar[t]   = fmaxf(ox2 - ox1, 0.0f) * fmaxf(oy2 - oy1, 0.0f);
        u.d.sc[t]   = sc;
        u.d.cf[t]   = cf;
    }
    if (t < 32) s_alive[t] = (t < 31) ? 0xFFFFFFFFu : 0x000000FFu;  // 1000 bits
    __syncthreads();

    if (t >= 256) return;                  // NMS runs on 8 warps only

    // thread t owns candidates 4t..4t+3: load offset coords + area into registers
    float4 ob[4];
    float oar[4];
    #pragma unroll
    for (int q = 0; q < 4; q++) {
        int c = 4 * t + q;
        float4 pb = u.d.pbox[c];
        float off = u.d.cf[c] * 10000.0f;  // same fp32 op as decode -> identical values
        ob[q] = make_float4(pb.x + off, pb.y + off, pb.z + off, pb.w + off);
        oar[q] = u.d.ar[c];
    }
    unsigned nib = (t < 250) ? 0xFu : 0u;  // candidates >= 1000 dead

    for (int it = 0; it < MAXDET; it++) {
        if (t < 32) {
            unsigned w = s_alive[t];
            int pos = w ? (t * 32 + __ffs(w) - 1) : (1 << 30);
            #pragma unroll
            for (int d = 16; d > 0; d >>= 1)
                pos = min(pos, __shfl_xor_sync(0xFFFFFFFFu, pos, d));
            if (t == 0) {
                s_best  = pos;
                s_bestS = (pos < TOPK) ? u.d.sc[pos] : 0.0f;
            }
        }
        BAR256();
        int bi = s_best;
        float bs = s_bestS;
        if (bs <= 0.0f) break;             // uniform; rest of output stays zero
        if (t == (bi >> 2)) {              // owner writes the output row
            float4 pb = u.d.pbox[bi];
            float* o = out + (size_t)(b * MAXDET + it) * 6;
            o[0] = pb.x; o[1] = pb.y; o[2] = pb.z; o[3] = pb.w;
            o[4] = bs;   o[5] = u.d.cf[bi];
        }
        // best box in offset coords (recomputed with identical fp32 ops)
        float4 bpb = u.d.pbox[bi];
        float boff = u.d.cf[bi] * 10000.0f;
        float bx1 = bpb.x + boff, by1 = bpb.y + boff;
        float bx2 = bpb.z + boff, by2 = bpb.w + boff;
        float bar_ = u.d.ar[bi];
        unsigned kill = 0;
        #pragma unroll
        for (int q = 0; q < 4; q++) {
            if ((nib >> q) & 1u) {
                float xx1 = fmaxf(bx1, ob[q].x), yy1 = fmaxf(by1, ob[q].y);
                float xx2 = fminf(bx2, ob[q].z), yy2 = fminf(by2, ob[q].w);
                float inter = fmaxf(xx2 - xx1, 0.0f) * fmaxf(yy2 - yy1, 0.0f);
                float iou = inter / (bar_ + oar[q] - inter + 1e-9f);
                if (iou >= 0.6f || (4 * t + q) == bi) kill |= 1u << q;
            }
        }
        if (kill) {
            nib &= ~kill;
            atomicAnd(&s_alive[t >> 3], ~(kill << ((t & 7) * 4)));
        }
        BAR256();
    }
}

// ---------------- launch ----------------
extern "C" void kernel_launch(void* const* d_in, const int* in_sizes, int n_in,
                              void* d_out, int out_size) {
    (void)in_sizes; (void)n_in; (void)out_size;
    const float* lg[5]; const float* bb[5]; const float* ct[5];
    for (int l = 0; l < 5; l++) {
        lg[l] = (const float*)d_in[3 * l + 0];
        bb[l] = (const float*)d_in[3 * l + 1];
        ct[l] = (const float*)d_in[3 * l + 2];
    }
    const float* iminfo = (const float*)d_in[15];
    float* out = (float*)d_out;

    init_kernel<<<dim3(67, NB), 256>>>(ct[0], ct[1], ct[2], ct[3], ct[4]);
    histA_kernel<<<dim3(336, NB), 256>>>(lg[0], lg[1], lg[2], lg[3], lg[4]);
    selB_kernel<<<dim3(336, NB), 256>>>(lg[0], lg[1], lg[2], lg[3], lg[4]);
    sortnms_kernel<<<NB, 1024>>>(bb[0], bb[1], bb[2], bb[3], bb[4], iminfo, out);  // ncu launch #4
}

// round 17
// speedup vs baseline: 1.3180x; 1.3180x over previous
#include <cuda_runtime.h>
#include <math.h>

#define NB 16
#define NC 80
#define NLOC 17064
#define NBUCK 4096
#define SEL_CAP 4096
#define TOPK 1000
#define MAXDET 100

// ---------------- static device scratch (no allocations) ----------------
__device__ int g_hist[NB * NBUCK];
__device__ int g_selCount[NB];
__device__ int g_done[NB];
__device__ int g_thr[NB];
__device__ float g_thrX[NB];
__device__ float g_cen[NB * NLOC];
__device__ unsigned long long g_sel[NB * SEL_CAP];   // (score_bits<<32)|(~idx)

// ---------------- init: zero hist/counters + centerness sigmoid ----------------
__global__ __launch_bounds__(256) void init_kernel(
    const float* __restrict__ ct0, const float* __restrict__ ct1,
    const float* __restrict__ ct2, const float* __restrict__ ct3,
    const float* __restrict__ ct4)
{
    int b = blockIdx.y;
    int bx = blockIdx.x;
    int t = threadIdx.x;
    if (bx < 16) g_hist[b * NBUCK + bx * 256 + t] = 0;
    if (bx == 0 && t == 0) { g_selCount[b] = 0; g_done[b] = 0; }
    int loc = bx * 256 + t;
    if (loc >= NLOC) return;
    const float* p; int local;
    if      (loc < 12800) { p = ct0 + b * 12800; local = loc; }
    else if (loc < 16000) { p = ct1 + b * 3200;  local = loc - 12800; }
    else if (loc < 16800) { p = ct2 + b * 800;   local = loc - 16000; }
    else if (loc < 17008) { p = ct3 + b * 208;   local = loc - 16800; }
    else                  { p = ct4 + b * 56;    local = loc - 17008; }
    float x = p[local];
    g_cen[b * NLOC + loc] = __fdividef(1.0f, 1.0f + __expf(-x));
}

// ---------------- pass A: histogram (smem-staged) + fused threshold ----------------
template<int HW, int LOCOFF>
__device__ __forceinline__ void hist_level(
    const float* __restrict__ lg, int b, int chunk, int* sh)
{
    constexpr int CHW = NC * HW;
    const float* lp = lg + (size_t)b * CHW;
    const float* cenp = g_cen + b * NLOC + LOCOFF;
    int e0 = chunk * 4096 + threadIdx.x * 4;
    float4 v[4];
    #pragma unroll
    for (int k = 0; k < 4; k++) {
        int e = e0 + k * 1024;
        v[k] = make_float4(-9e9f, -9e9f, -9e9f, -9e9f);
        if (e < CHW) v[k] = *reinterpret_cast<const float4*>(lp + e);
    }
    #pragma unroll
    for (int k = 0; k < 4; k++) {
        int e = e0 + k * 1024;
        int c  = e / HW;
        int hw = e - c * HW;
        float xs[4] = {v[k].x, v[k].y, v[k].z, v[k].w};
        #pragma unroll
        for (int i = 0; i < 4; i++) {
            float x = xs[i];
            if (x > -2.9445f) {                  // sigmoid(-2.9445) < 0.05 w/ margin
                float cls = __fdividef(1.0f, 1.0f + __expf(-x));
                if (cls > 0.05f) {
                    float comb = cls * cenp[hw + i];
                    atomicAdd(&sh[__float_as_uint(comb) >> 19], 1);
                }
            }
        }
    }
}

__global__ __launch_bounds__(256) void histA_kernel(
    const float* __restrict__ lg0, const float* __restrict__ lg1,
    const float* __restrict__ lg2, const float* __restrict__ lg3,
    const float* __restrict__ lg4)
{
    __shared__ int sh[NBUCK];
    __shared__ int s_last;
    int t = threadIdx.x;
    #pragma unroll
    for (int q = 0; q < NBUCK / 256; q++) sh[q * 256 + t] = 0;
    __syncthreads();

    int bx = blockIdx.x, b = blockIdx.y;
    if      (bx < 250) hist_level<12800,     0>(lg0, b, bx,       sh);
    else if (bx < 313) hist_level< 3200, 12800>(lg1, b, bx - 250, sh);
    else if (bx < 329) hist_level<  800, 16000>(lg2, b, bx - 313, sh);
    else if (bx < 334) hist_level<  208, 16800>(lg3, b, bx - 329, sh);
    else               hist_level<   56, 17008>(lg4, b, bx - 334, sh);
    __syncthreads();

    int* gh = &g_hist[b * NBUCK];
    #pragma unroll
    for (int q = 0; q < NBUCK / 256; q++) {
        int v = sh[q * 256 + t];
        if (v) atomicAdd(&gh[q * 256 + t], v);
    }

    // fused threshold: last block of this batch scans the histogram
    __threadfence();
    if (t == 0) s_last = (atomicAdd(&g_done[b], 1) == 335);
    __syncthreads();
    if (!s_last) return;

    int s = 0;
    for (int r = t * 16; r < t * 16 + 16; r++)
        s += gh[NBUCK - 1 - r];
    sh[t] = s;
    __syncthreads();
    if (t == 0) {
        int cum = 0, j = 255;
        for (int q = 0; q < 256; q++) {
            if (cum + sh[q] >= TOPK) { j = q; break; }
            cum += sh[q];
        }
        sh[300] = j; sh[301] = cum;
    }
    __syncthreads();
    int j = sh[300];
    if (t < 16) sh[256 + t] = gh[NBUCK - 1 - (j * 16 + t)];
    __syncthreads();
    if (t == 0) {
        int cum = sh[301], thr = 0;
        for (int q = 0; q < 16; q++) {
            cum += sh[256 + q];
            if (cum >= TOPK) { thr = NBUCK - 1 - (j * 16 + q); break; }
        }
        g_thr[b] = thr;                          // 0 => take everything
        float tX = -2.9445f;
        if (thr > 0) {
            float cm = __uint_as_float((unsigned)thr << 19);  // bucket lower edge
            if (cm > 0.0f && cm < 1.0f)
                tX = fmaxf(tX, logf(cm / (1.0f - cm)) - 1e-3f); // cls >= comb >= cm
        }
        g_thrX[b] = tX;
    }
}

// ---------------- pass B: selective re-read, direct candidate write ----------------
template<int HW, int LOCOFF>
__device__ __forceinline__ void sel_level(
    const float* __restrict__ lg, int b, int chunk, unsigned thr, float thrX)
{
    constexpr int CHW = NC * HW;
    const float* lp = lg + (size_t)b * CHW;
    const float* cenp = g_cen + b * NLOC + LOCOFF;
    int e0 = chunk * 4096 + threadIdx.x * 4;
    float4 v[4];
    #pragma unroll
    for (int k = 0; k < 4; k++) {
        int e = e0 + k * 1024;
        v[k] = make_float4(-9e9f, -9e9f, -9e9f, -9e9f);
        if (e < CHW) v[k] = *reinterpret_cast<const float4*>(lp + e);
    }
    #pragma unroll
    for (int k = 0; k < 4; k++) {
        int e = e0 + k * 1024;
        int c  = e / HW;
        int hw = e - c * HW;
        float xs[4] = {v[k].x, v[k].y, v[k].z, v[k].w};
        #pragma unroll
        for (int i = 0; i < 4; i++) {
            float x = xs[i];
            if (x > thrX) {
                float cls = __fdividef(1.0f, 1.0f + __expf(-x));
                if (cls > 0.05f) {
                    float comb = cls * cenp[hw + i];
                    unsigned bits = __float_as_uint(comb);
                    if ((bits >> 19) >= thr) {
                        unsigned idx = (unsigned)((LOCOFF + hw + i) * NC + c);
                        int p = atomicAdd(&g_selCount[b], 1);
                        if (p < SEL_CAP)
                            g_sel[b * SEL_CAP + p] =
                                ((unsigned long long)bits << 32) |
                                (unsigned long long)(0xFFFFFFFFu - idx);
                    }
                }
            }
        }
    }
}

__global__ __launch_bounds__(256) void selB_kernel(
    const float* __restrict__ lg0, const float* __restrict__ lg1,
    const float* __restrict__ lg2, const float* __restrict__ lg3,
    const float* __restrict__ lg4)
{
    int bx = blockIdx.x, b = blockIdx.y;
    unsigned thr = (unsigned)g_thr[b];
    float thrX = g_thrX[b];
    if      (bx < 250) sel_level<12800,     0>(lg0, b, bx,       thr, thrX);
    else if (bx < 313) sel_level< 3200, 12800>(lg1, b, bx - 250, thr, thrX);
    else if (bx < 329) sel_level<  800, 16000>(lg2, b, bx - 313, thr, thrX);
    else if (bx < 334) sel_level<  208, 16800>(lg3, b, bx - 329, thr, thrX);
    else               sel_level<   56, 17008>(lg4, b, bx - 334, thr, thrX);
}

// ---------------- fused radix-select + 1024-sort + decode + 1-barrier NMS ----------------
__global__ __launch_bounds__(1024) void sortnms_kernel(
    const float* __restrict__ bb0, const float* __restrict__ bb1,
    const float* __restrict__ bb2, const float* __restrict__ bb3,
    const float* __restrict__ bb4, const float* __restrict__ iminfo,
    float* __restrict__ out)
{
    int b = blockIdx.x;
    int t = threadIdx.x;
    int lane = t & 31;

    __shared__ union {
        unsigned long long key[SEL_CAP];                  // 32 KB
        struct { float4 obox[1024];                       // 16 KB offset coords
                 float ar[1024], sc[1024]; } d;           // + 8 KB
    } u;
    __shared__ unsigned long long buf[1024];              // 8 KB
    __shared__ unsigned s_alive[32];
    __shared__ unsigned long long s_pivot;
    __shared__ int s_kneed, s_c2;
    __shared__ int h256[256];

    // pre-zero this batch's output (100 rows x 6)
    if (t < MAXDET * 6) out[(size_t)b * MAXDET * 6 + t] = 0.0f;

    int cnt = min(g_selCount[b], SEL_CAP);
    buf[t] = 0ULL;
    for (int i = t; i < cnt; i += 1024)
        u.key[i] = g_sel[b * SEL_CAP + i];
    if (t == 0) { s_pivot = 0ULL; s_kneed = TOPK; s_c2 = 0; }
    __syncthreads();

    if (cnt > 1024) {
        // exact radix-select: 1000th-largest 64-bit key (keys unique)
        for (int byte = 7; byte >= 0; byte--) {
            if (t < 256) h256[t] = 0;
            __syncthreads();
            unsigned long long piv = s_pivot;
            int shb = byte * 8;
            unsigned long long himask = (byte == 7) ? 0ULL
                : (0xFFFFFFFFFFFFFFFFULL << (8 * (byte + 1)));
            for (int i = t; i < cnt; i += 1024) {
                unsigned long long kk = u.key[i];
                if ((kk & himask) == piv)
                    atomicAdd(&h256[(int)((kk >> shb) & 0xFF)], 1);
            }
            __syncthreads();
            if (t < 32) {
                int g0 = 255 - 8 * t;
                int gs = 0;
                #pragma unroll
                for (int q = 0; q < 8; q++) gs += h256[g0 - q];
                int pre = gs;
                #pragma unroll
                for (int d = 1; d < 32; d <<= 1) {
                    int x = __shfl_up_sync(0xFFFFFFFFu, pre, d);
                    if (t >= d) pre += x;
                }
                int excl = pre - gs;
                int k = s_kneed;
                bool hit = (excl < k) && (excl + gs >= k);
                if (hit) {
                    int need = k - excl, acc = 0;
                    #pragma unroll
                    for (int q = 0; q < 8; q++) {
                        int c = h256[g0 - q];
                        if (acc + c >= need) {
                            s_pivot = piv | ((unsigned long long)(g0 - q) << shb);
                            s_kneed = need - acc;
                            break;
                        }
                        acc += c;
                    }
                }
            }
            __syncthreads();
        }
        // compact exactly TOPK keys >= pivot
        unsigned long long piv = s_pivot;
        for (int i = t; (i - lane) < cnt; i += 1024) {
            bool take = (i < cnt) && (u.key[i] >= piv);
            unsigned m = __ballot_sync(0xFFFFFFFFu, take);
            if (m) {
                int leader = __ffs(m) - 1;
                int base = 0;
                if (lane == leader) base = atomicAdd(&s_c2, __popc(m));
                base = __shfl_sync(0xFFFFFFFFu, base, leader);
                if (take) {
                    int p = base + __popc(m & ((1u << lane) - 1u));
                    if (p < 1024) buf[p] = u.key[i];
                }
            }
        }
    } else {
        if (t < cnt) buf[t] = u.key[t];
    }
    __syncthreads();

    // register-resident bitonic sort of 1024 (descending)
    unsigned long long v = buf[t];
    for (int k = 2; k <= 1024; k <<= 1) {
        bool desc = (t & k) == 0;
        for (int j = k >> 1; j > 0; j >>= 1) {
            unsigned long long p;
            if (j >= 32) {
                __syncthreads();
                buf[t] = v;
                __syncthreads();
                p = buf[t ^ j];
            } else {
                p = __shfl_xor_sync(0xFFFFFFFFu, v, j);
            }
            bool keepmax = ((t & j) == 0) == desc;
            bool pgt = p > v;
            if (pgt == keepmax) v = p;
        }
    }
    unsigned long long myKey = v;          // rank t (desc score, asc idx ties)
    __syncthreads();                       // sort reads done; arrays may overwrite key

    // decode: own box kept in registers; broadcast arrays in smem
    float rx1 = 0.f, ry1 = 0.f, rx2 = 0.f, ry2 = 0.f, rsc = 0.f, rcf = 0.f;
    float rox1 = 0.f, roy1 = 0.f, rox2 = 0.f, roy2 = 0.f, rar = 0.f;
    {
        unsigned bits = (unsigned)(myKey >> 32);
        if (bits != 0u) {
            unsigned idx = 0xFFFFFFFFu - (unsigned)(myKey & 0xFFFFFFFFu);
            int loc = (int)(idx / NC);
            int c   = (int)(idx % NC);
            const int offs[5]    = {0, 12800, 16000, 16800, 17008};
            const int Ws[5]      = {128, 64, 32, 16, 8};
            const int HWs[5]     = {12800, 3200, 800, 208, 56};
            const int strides[5] = {8, 16, 32, 64, 128};
            const float* bbs[5]  = {bb0, bb1, bb2, bb3, bb4};
            int lvl = 4;
            if      (loc < 12800) lvl = 0;
            else if (loc < 16000) lvl = 1;
            else if (loc < 16800) lvl = 2;
            else if (loc < 17008) lvl = 3;
            int local = loc - offs[lvl];
            int W = Ws[lvl], HW = HWs[lvl], st = strides[lvl];
            int hh = local / W;
            int ww = local - hh * W;
            float cx = (float)(ww * st + (st >> 1));
            float cy = (float)(hh * st + (st >> 1));
            const float* bp = bbs[lvl] + (size_t)b * 4 * HW + local;
            float r0 = bp[0], r1 = bp[HW], r2 = bp[2 * HW], r3 = bp[3 * HW];
            float ih = iminfo[b * 2 + 0];
            float iw = iminfo[b * 2 + 1];
            rx1 = fminf(fmaxf(cx - r0, 0.0f), iw - 1.0f);
            ry1 = fminf(fmaxf(cy - r1, 0.0f), ih - 1.0f);
            rx2 = fminf(fmaxf(cx + r2, 0.0f), iw - 1.0f);
            ry2 = fminf(fmaxf(cy + r3, 0.0f), ih - 1.0f);
            rsc = sqrtf(__uint_as_float(bits) + 1e-12f);
            rcf = (float)c;
        }
        float off = rcf * 10000.0f;
        rox1 = rx1 + off; roy1 = ry1 + off; rox2 = rx2 + off; roy2 = ry2 + off;
        rar  = fmaxf(rox2 - rox1, 0.0f) * fmaxf(roy2 - roy1, 0.0f);
        u.d.obox[t] = make_float4(rox1, roy1, rox2, roy2);
        u.d.ar[t]   = rar;
        u.d.sc[t]   = rsc;
    }
    if (t < 32) s_alive[t] = (t < 31) ? 0xFFFFFFFFu : 0x000000FFu;  // 1000 bits
    __syncthreads();

    // sorted-greedy NMS, ONE barrier per iteration:
    // every warp redundantly computes the block-uniform first-alive (argmax).
    bool myalive = (t < TOPK);
    for (int it = 0; it < MAXDET; it++) {
        unsigned w = s_alive[lane];            // lane i reads bitmap word i
        int pos = w ? (lane * 32 + __ffs(w) - 1) : (1 << 30);
        #pragma unroll
        for (int d = 16; d > 0; d >>= 1)
            pos = min(pos, __shfl_xor_sync(0xFFFFFFFFu, pos, d));
        int bi = pos;
        int bic = (bi < 1024) ? bi : 0;
        float bs = (bi < TOPK) ? u.d.sc[bic] : 0.0f;   // LDS broadcast
        if (bs <= 0.0f) break;                 // uniform; rest of output stays zero
        if (t == bi) {                          // winner writes its own row
            float* o = out + (size_t)(b * MAXDET + it) * 6;
            o[0] = rx1; o[1] = ry1; o[2] = rx2; o[3] = ry2; o[4] = rsc; o[5] = rcf;
        }
        unsigned act = __ballot_sync(0xFFFFFFFFu, myalive);
        bool sup = false;
        if (act) {                              // whole-warp dead skip
            float4 bb = u.d.obox[bic];          // one LDS.128 broadcast
            float bar_ = u.d.ar[bic];
            if (myalive) {
                float xx1 = fmaxf(bb.x, rox1), yy1 = fmaxf(bb.y, roy1);
                float xx2 = fminf(bb.z, rox2), yy2 = fminf(bb.w, roy2);
                float inter = fmaxf(xx2 - xx1, 0.0f) * fmaxf(yy2 - yy1, 0.0f);
                float iou = inter / (bar_ + rar - inter + 1e-9f);
                sup = (iou >= 0.6f) || (t == bi);
            }
        }
        unsigned m = __ballot_sync(0xFFFFFFFFu, sup);
        if (lane == 0 && m) s_alive[t >> 5] &= ~m;   // warp w owns word w
        if (sup) myalive = false;
        __syncthreads();
    }
}

// ---------------- launch ----------------
extern "C" void kernel_launch(void* const* d_in, const int* in_sizes, int n_in,
                              void* d_out, int out_size) {
    (void)in_sizes; (void)n_in; (void)out_size;
    const float* lg[5]; const float* bb[5]; const float* ct[5];
    for (int l = 0; l < 5; l++) {
        lg[l] = (const float*)d_in[3 * l + 0];
        bb[l] = (const float*)d_in[3 * l + 1];
        ct[l] = (const float*)d_in[3 * l + 2];
    }
    const float* iminfo = (const float*)d_in[15];
    float* out = (float*)d_out;

    init_kernel<<<dim3(67, NB), 256>>>(ct[0], ct[1], ct[2], ct[3], ct[4]);
    histA_kernel<<<dim3(336, NB), 256>>>(lg[0], lg[1], lg[2], lg[3], lg[4]);
    selB_kernel<<<dim3(336, NB), 256>>>(lg[0], lg[1], lg[2], lg[3], lg[4]);
    sortnms_kernel<<<NB, 1024>>>(bb[0], bb[1], bb[2], bb[3], bb[4], iminfo, out);  // ncu launch #4
}